// round 14
// baseline (speedup 1.0000x reference)
#include <cuda_runtime.h>

#define B 8
#define E 2000
#define NT 10000
#define NRELS 25
#define KT 16
#define TT 3
#define LL 32

// ---------------- scratch (device globals; no allocs allowed) ----------------
__device__ int   g_heads[NT];
__device__ int   g_tails[NT];
__device__ int   g_rels[NT];
__device__ int   g_ent[B];
__device__ int   g_tidx[E];
__device__ int   g_emask[E];     // bit r set iff exists triple tail=e, rel=r (r<24)
__device__ int   g_bmask[B];     // bit r set iff exists triple head=ent[b], rel=r
__device__ int   g_act0[E];      // bit b set iff r0[e][b][:] may be nonzero
__device__ int   g_act1[E];      // bit b set iff r1[e][b][:] may be nonzero
__device__ float g_hidx[B * LL]; // hidden_x at t=0
__device__ float g_r0[E * B * LL];  // s buffers [e][b][l]
__device__ float g_r1[E * B * LL];
__device__ float g_r2[E * B * LL];

__device__ __forceinline__ float clip01(float x) { return fminf(fmaxf(x, 0.f), 1.f); }

// on-the-fly softmax(w[t][lane])[r]  (two-pass over 25 L1-hot values)
__device__ __forceinline__ float wp_f(const float* __restrict__ w, int t, int lane, int r) {
    const float* row = w + (t * LL + lane) * NRELS;
    float m = -1e30f;
#pragma unroll
    for (int j = 0; j < NRELS; j++) m = fmaxf(m, row[j]);
    float s = 0.f;
#pragma unroll
    for (int j = 0; j < NRELS; j++) s += __expf(row[j] - m);
    return __expf(row[r] - m) * __frcp_rn(s);
}

// on-the-fly hidden gate hidden[t][e][lane]
__device__ __forceinline__ float hidden_f(const float* __restrict__ h,
                                          const float* __restrict__ htype,
                                          const float* __restrict__ alpha,
                                          const float* __restrict__ beta,
                                          int t, int e, int lane) {
    float a  = clip01(alpha[t * LL + lane] * 0.1f);
    float bb = clip01(beta[t * LL + lane] * 0.1f);
    int k = g_tidx[e];
    float htp = clip01(htype[(t * LL + lane) * KT + k] * 0.1f);
    int mask = g_emask[e];
    float acc = 0.f;
#pragma unroll
    for (int j = 0; j < 24; j++)
        if (mask & (1 << j)) acc += clip01(h[(t * LL + lane) * 24 + j] * 0.1f);
    return clip01(a * htp + bb * acc) + (1.f - clip01(a + bb));
}

// ======== K1: high-occupancy 160MB streaming scan + scratch zeroing ========
__global__ void k_extract(const float* __restrict__ inx, const float* __restrict__ tmat,
                          const float4* __restrict__ e2t, const float4* __restrict__ t2e,
                          const float* __restrict__ t2r) {
    int st = gridDim.x * blockDim.x, i0 = blockIdx.x * blockDim.x + threadIdx.x;
    for (int i = i0; i < E * B * LL; i += st) { g_r0[i] = 0.f; g_r1[i] = 0.f; g_r2[i] = 0.f; }
    for (int i = i0; i < E; i += st) { g_emask[i] = 0; g_act0[i] = 0; g_act1[i] = 0; }
    if (i0 < B) g_bmask[i0] = 0;

    const int NE4 = E * NT / 4;   // 5M float4 per big matrix
    // e2triple [E][NT]: nonzero at (heads[n], n); NT%4==0 keeps float4 in-row
    for (int i = i0; i < NE4; i += st) {
        float4 v = __ldcs(&e2t[i]);
        if (v.x != 0.f || v.y != 0.f || v.z != 0.f || v.w != 0.f) {
            int idx = i * 4; int e = idx / NT; int n = idx - e * NT;
            if (v.x != 0.f) g_heads[n]     = e;
            if (v.y != 0.f) g_heads[n + 1] = e;
            if (v.z != 0.f) g_heads[n + 2] = e;
            if (v.w != 0.f) g_heads[n + 3] = e;
        }
    }
    // triple2e [NT][E]: nonzero at (n, tails[n]); E%4==0
    for (int i = i0; i < NE4; i += st) {
        float4 v = __ldcs(&t2e[i]);
        if (v.x != 0.f || v.y != 0.f || v.z != 0.f || v.w != 0.f) {
            int idx = i * 4; int n = idx / E; int e = idx - n * E;
            if (v.x != 0.f) g_tails[n] = e;
            if (v.y != 0.f) g_tails[n] = e + 1;
            if (v.z != 0.f) g_tails[n] = e + 2;
            if (v.w != 0.f) g_tails[n] = e + 3;
        }
    }
    for (int i = i0; i < NT * NRELS; i += st)
        if (__ldcs(&t2r[i]) != 0.f) g_rels[i / NRELS] = i % NRELS;
    for (int i = i0; i < E * KT; i += st)
        if (tmat[i] != 0.f) g_tidx[i / KT] = i % KT;
    for (int i = i0; i < B * E; i += st)
        if (inx[i] != 0.f) g_ent[i / E] = i % E;
}

// ======== K2: indicator bitmasks ========
__global__ void k_flags() {
    int n = blockIdx.x * 256 + threadIdx.x;
    if (n >= NT) return;
    int r = g_rels[n], tl = g_tails[n], hd = g_heads[n];
    if (r < NRELS - 1) atomicOr(&g_emask[tl], 1 << r);
    int bit = 1 << r;
#pragma unroll
    for (int b = 0; b < B; b++)
        if (hd == g_ent[b]) atomicOr(&g_bmask[b], bit);
}

// ======== K3: prop0 (warp per triple) + hidden_x block ========
// r0[tails[n]][b][lane] += softmax(w[0][lane])[rels[n]] if heads[n]==ent[b]
__global__ void k_prop0(const float* __restrict__ w,
                        const float* __restrict__ hx, const float* __restrict__ hxtype,
                        const float* __restrict__ alpha, const float* __restrict__ beta,
                        const float* __restrict__ alphax, const float* __restrict__ betax) {
    if (blockIdx.x == 1250) {    // hidden_x at t=0 (256 threads = B*LL)
        int i = threadIdx.x;
        int b = i / LL, l = i % LL;
        float a0 = clip01(alpha[l] * 0.1f), b0 = clip01(beta[l] * 0.1f);
        int k = g_tidx[g_ent[b]];
        float htx = clip01(hxtype[l * KT + k] * 0.1f);
        int mask = g_bmask[b];
        float acc = 0.f;
#pragma unroll
        for (int j = 0; j < 24; j++) {
            int src = (j < 12) ? (j + 12) : (j - 12);  // concat(hx_raw[:,12:24], hx_raw[:,:12])
            if (mask & (1 << src)) acc += clip01(hx[l * 24 + j] * 0.1f);
        }
        float gate = 1.f - clip01(clip01(alphax[l] * 0.1f) + clip01(betax[l] * 0.1f));
        g_hidx[i] = clip01(a0 * htx + b0 * acc) + gate;
        return;
    }
    int n = blockIdx.x * 8 + (threadIdx.x >> 5);
    int lane = threadIdx.x & 31;
    int hn = g_heads[n];
    int entv[B];
#pragma unroll
    for (int b = 0; b < B; b++) entv[b] = g_ent[b];
    unsigned bits = 0;
#pragma unroll
    for (int b = 0; b < B; b++) if (entv[b] == hn) bits |= 1u << b;
    if (!bits) return;
    int tl = g_tails[n];
    float wv = wp_f(w, 0, lane, g_rels[n]);
#pragma unroll
    for (int b = 0; b < B; b++)
        if (entv[b] == hn) atomicAdd(&g_r0[(tl * B + b) * LL + lane], wv);
    if (lane == 0) atomicOr(&g_act0[tl], (int)bits);
}

// ======== K4/K5: propagation with activity skip; gates computed lazily ========
template <int STEP>
__global__ void k_prop(const float* __restrict__ w, const float* __restrict__ h,
                       const float* __restrict__ htype,
                       const float* __restrict__ alpha, const float* __restrict__ beta) {
    int n = blockIdx.x * 8 + (threadIdx.x >> 5);
    int lane = threadIdx.x & 31;
    int hn = g_heads[n];
    int act = (STEP == 1) ? g_act0[hn] : g_act1[hn];
    if (!act) return;                                   // frontier skip (vast majority)
    const float* src = (STEP == 1) ? g_r0 : g_r1;
    float*       dst = (STEP == 1) ? g_r1 : g_r2;
    int tl = g_tails[n], r = g_rels[n];
    float hv = hidden_f(h, htype, alpha, beta, STEP - 1, hn, lane)
             * wp_f(w, STEP, lane, r);
#pragma unroll
    for (int b = 0; b < B; b++) {
        if (act & (1 << b)) {
            float v = src[(hn * B + b) * LL + lane];
            if (v != 0.f) {
                float x = v * hv;
                if (STEP == 1) x *= g_hidx[b * LL + lane];
                atomicAdd(&dst[(tl * B + b) * LL + lane], x);
            }
        }
    }
    if (STEP == 1 && lane == 0) atomicOr(&g_act1[tl], act);   // superset is safe
}

// ======== K6: epilogue with zero skip ========
__global__ void k_out(const float* __restrict__ weight, const float* __restrict__ h,
                      const float* __restrict__ htype,
                      const float* __restrict__ alpha, const float* __restrict__ beta,
                      float* __restrict__ out) {
    int idx = blockIdx.x * 8 + (threadIdx.x >> 5);   // warp per (b,e)
    if (idx >= B * E) return;
    int lane = threadIdx.x & 31;
    int e = idx % E, b = idx / E;
    float v = g_r2[(e * B + b) * LL + lane];
    unsigned ball = __ballot_sync(0xffffffffu, v != 0.f);
    if (!ball) { if (lane == 0) out[b * E + e] = 0.f; return; }
    v *= hidden_f(h, htype, alpha, beta, 2, e, lane) * tanhf(weight[lane]);
#pragma unroll
    for (int o = 16; o > 0; o >>= 1) v += __shfl_down_sync(0xffffffffu, v, o);
    if (lane == 0) out[b * E + e] = v;
}

extern "C" void kernel_launch(void* const* d_in, const int* in_sizes, int n_in,
                              void* d_out, int out_size) {
    const float* inx    = (const float*)d_in[0];   // input_x   [8,2000]
    const float* tmat   = (const float*)d_in[1];   // type_mat  [2000,16]
    const float* e2t    = (const float*)d_in[2];   // e2triple  [2000,10000]
    const float* t2e    = (const float*)d_in[3];   // triple2e  [10000,2000]
    const float* t2r    = (const float*)d_in[4];   // triple2r  [10000,25]
    const float* w      = (const float*)d_in[5];   // [3,32,25]
    const float* weight = (const float*)d_in[6];   // [32,1]
    const float* h      = (const float*)d_in[7];   // [3,32,24]
    const float* hx     = (const float*)d_in[8];   // [32,24]
    const float* htype  = (const float*)d_in[9];   // [3,32,16]
    const float* hxtype = (const float*)d_in[10];  // [32,16]
    const float* alpha  = (const float*)d_in[11];  // [3,32]
    const float* beta   = (const float*)d_in[12];  // [3,32]
    const float* alphax = (const float*)d_in[13];  // [32]
    const float* betax  = (const float*)d_in[14];  // [32]
    float* out = (float*)d_out;

    k_extract<<<2048, 256>>>(inx, tmat, (const float4*)e2t, (const float4*)t2e, t2r);
    k_flags<<<40, 256>>>();
    k_prop0<<<1251, 256>>>(w, hx, hxtype, alpha, beta, alphax, betax);
    k_prop<1><<<1250, 256>>>(w, h, htype, alpha, beta);  // r0->r1: hidden0*hidx, wp1
    k_prop<2><<<1250, 256>>>(w, h, htype, alpha, beta);  // r1->r2: hidden1, wp2
    k_out<<<2000, 256>>>(weight, h, htype, alpha, beta, out);
}

// round 16
// speedup vs baseline: 1.0553x; 1.0553x over previous
#include <cuda_runtime.h>

#define B 8
#define E 2000
#define NT 10000
#define NRELS 25
#define KT 16
#define TT 3
#define LL 32

// ---------------- scratch (device globals; no allocs allowed) ----------------
__device__ int   g_heads[NT];
__device__ int   g_tails[NT];
__device__ int   g_rels[NT];
__device__ int   g_ent[B];
__device__ int   g_tidx[E];
__device__ int   g_emask[E];             // bit r set iff exists triple tail=e, rel=r (r<24)
__device__ int   g_bmask[B];             // bit r set iff exists triple head=ent[b], rel=r
__device__ int   g_act0[E];              // bit b set iff r0[e][b][:] nonzero
__device__ int   g_act1[E];              // bit b set iff r1[e][b][:] may be nonzero (superset)
__device__ int   g_act2[E];              // bit b set iff r2[e][b][:] may be nonzero (superset)
__device__ float g_wp[TT * LL * NRELS];  // softmax(w[t]) [t][l][r]
__device__ float g_tanhw[LL];
__device__ float g_hidx[B * LL];         // hidden_x at t=0
__device__ float g_hidden[TT * E * LL];  // hidden gates [t][e][l]
__device__ float g_r0[E * B * LL];       // s buffers [e][b][l]
__device__ float g_r1[E * B * LL];
__device__ float g_r2[E * B * LL];

__device__ __forceinline__ float clip01(float x) { return fminf(fmaxf(x, 0.f), 1.f); }

// ======== K1: high-occupancy 160MB streaming scan + scratch zeroing ========
__global__ void k_extract(const float* __restrict__ inx, const float* __restrict__ tmat,
                          const float4* __restrict__ e2t, const float4* __restrict__ t2e,
                          const float* __restrict__ t2r) {
    int st = gridDim.x * blockDim.x, i0 = blockIdx.x * blockDim.x + threadIdx.x;
    // zero scratch (disjoint from scan outputs)
    for (int i = i0; i < E * B * LL; i += st) { g_r0[i] = 0.f; g_r1[i] = 0.f; g_r2[i] = 0.f; }
    for (int i = i0; i < E; i += st) { g_emask[i] = 0; g_act0[i] = 0; g_act1[i] = 0; g_act2[i] = 0; }
    if (i0 < B) g_bmask[i0] = 0;

    const int NE4 = E * NT / 4;   // 5M float4 per big matrix
    // e2triple [E][NT]: nonzero at (heads[n], n); NT%4==0 keeps float4 in-row
    for (int i = i0; i < NE4; i += st) {
        float4 v = __ldcs(&e2t[i]);                       // streaming: read-once
        if (v.x != 0.f || v.y != 0.f || v.z != 0.f || v.w != 0.f) {
            int idx = i * 4; int e = idx / NT; int n = idx - e * NT;
            if (v.x != 0.f) g_heads[n]     = e;
            if (v.y != 0.f) g_heads[n + 1] = e;
            if (v.z != 0.f) g_heads[n + 2] = e;
            if (v.w != 0.f) g_heads[n + 3] = e;
        }
    }
    // triple2e [NT][E]: nonzero at (n, tails[n]); E%4==0
    for (int i = i0; i < NE4; i += st) {
        float4 v = __ldcs(&t2e[i]);
        if (v.x != 0.f || v.y != 0.f || v.z != 0.f || v.w != 0.f) {
            int idx = i * 4; int n = idx / E; int e = idx - n * E;
            if (v.x != 0.f) g_tails[n] = e;
            if (v.y != 0.f) g_tails[n] = e + 1;
            if (v.z != 0.f) g_tails[n] = e + 2;
            if (v.w != 0.f) g_tails[n] = e + 3;
        }
    }
    for (int i = i0; i < NT * NRELS; i += st)
        if (__ldcs(&t2r[i]) != 0.f) g_rels[i / NRELS] = i % NRELS;
    for (int i = i0; i < E * KT; i += st)
        if (tmat[i] != 0.f) g_tidx[i / KT] = i % KT;
    for (int i = i0; i < B * E; i += st)
        if (inx[i] != 0.f) g_ent[i / E] = i % E;
}

// ======== K2: indicator bitmasks + softmax(w) + tanh(weight) ========
// blocks [0,40): flags over triples; block 40: softmax + tanh
__global__ void k_flags(const float* __restrict__ w, const float* __restrict__ weight) {
    if (blockIdx.x < 40) {
        int n = blockIdx.x * 256 + threadIdx.x;
        if (n >= NT) return;
        int r = g_rels[n], tl = g_tails[n], hd = g_heads[n];
        if (r < NRELS - 1) atomicOr(&g_emask[tl], 1 << r);
        int bit = 1 << r;
#pragma unroll
        for (int b = 0; b < B; b++)
            if (hd == g_ent[b]) atomicOr(&g_bmask[b], bit);
        return;
    }
    int i = threadIdx.x;
    if (i < TT * LL) {          // softmax of w[t][l][:25]
        float vals[NRELS]; float m = -1e30f;
#pragma unroll
        for (int r = 0; r < NRELS; r++) { vals[r] = w[i * NRELS + r]; m = fmaxf(m, vals[r]); }
        float s = 0.f;
#pragma unroll
        for (int r = 0; r < NRELS; r++) { vals[r] = __expf(vals[r] - m); s += vals[r]; }
        float inv = __frcp_rn(s);
#pragma unroll
        for (int r = 0; r < NRELS; r++) g_wp[i * NRELS + r] = vals[r] * inv;
    }
    if (i >= 96 && i < 96 + LL) g_tanhw[i - 96] = tanhf(weight[i - 96]);
}

// ======== K3: hidden gates + hidden_x(t=0) + prop0 (independent outputs) ========
// blocks [0,750): hidden[t][e][l]; block 750: hidden_x; blocks [751,751+1250): prop0
__global__ void k_gates(const float* __restrict__ h, const float* __restrict__ htype,
                        const float* __restrict__ alpha, const float* __restrict__ beta,
                        const float* __restrict__ hx, const float* __restrict__ hxtype,
                        const float* __restrict__ alphax, const float* __restrict__ betax) {
    if (blockIdx.x < 750) {
        int z = blockIdx.x * 256 + threadIdx.x;       // z < 192000 = TT*E*LL exactly
        int l = z & 31; int rest = z >> 5; int e = rest % E; int t = rest / E;
        float a  = clip01(alpha[t * LL + l] * 0.1f);
        float bb = clip01(beta[t * LL + l] * 0.1f);
        int k = g_tidx[e];
        float htp = clip01(htype[(t * LL + l) * KT + k] * 0.1f);
        int mask = g_emask[e];
        float acc = 0.f;
#pragma unroll
        for (int j = 0; j < 24; j++)
            if (mask & (1 << j)) acc += clip01(h[(t * LL + l) * 24 + j] * 0.1f);
        g_hidden[(t * E + e) * LL + l] = clip01(a * htp + bb * acc) + (1.f - clip01(a + bb));
        return;
    }
    if (blockIdx.x == 750) {    // hidden_x at t=0 (256 threads = B*LL)
        int i = threadIdx.x;
        int b = i / LL, l = i % LL;
        float a0 = clip01(alpha[l] * 0.1f), b0 = clip01(beta[l] * 0.1f);
        int k = g_tidx[g_ent[b]];
        float htx = clip01(hxtype[l * KT + k] * 0.1f);
        int mask = g_bmask[b];
        float acc = 0.f;
#pragma unroll
        for (int j = 0; j < 24; j++) {
            int src = (j < 12) ? (j + 12) : (j - 12);  // concat(hx_raw[:,12:24], hx_raw[:,:12])
            if (mask & (1 << src)) acc += clip01(hx[l * 24 + j] * 0.1f);
        }
        float gate = 1.f - clip01(clip01(alphax[l] * 0.1f) + clip01(betax[l] * 0.1f));
        g_hidx[i] = clip01(a0 * htx + b0 * acc) + gate;
        return;
    }
    // prop0: warp per triple. r0[tails[n]][b][lane] += wp0[lane][rels[n]] if heads[n]==ent[b]
    int n = (blockIdx.x - 751) * 8 + (threadIdx.x >> 5);
    if (n >= NT) return;
    int lane = threadIdx.x & 31;
    int hn = g_heads[n];
    int entv[B];
#pragma unroll
    for (int b = 0; b < B; b++) entv[b] = g_ent[b];
    unsigned bits = 0;
#pragma unroll
    for (int b = 0; b < B; b++) if (entv[b] == hn) bits |= 1u << b;
    if (!bits) return;
    int tl = g_tails[n];
    float wv = g_wp[lane * NRELS + g_rels[n]];
#pragma unroll
    for (int b = 0; b < B; b++)
        if (entv[b] == hn) atomicAdd(&g_r0[(tl * B + b) * LL + lane], wv);
    if (lane == 0) atomicOr(&g_act0[tl], (int)bits);
}

// ======== K4/K5: propagation with activity skip; cheap precomputed gates ========
template <int STEP>
__global__ void k_prop() {
    int n = blockIdx.x * 8 + (threadIdx.x >> 5);
    int lane = threadIdx.x & 31;
    int hn = g_heads[n];
    int act = (STEP == 1) ? g_act0[hn] : g_act1[hn];
    if (!act) return;                                   // frontier skip (vast majority)
    const float* src = (STEP == 1) ? g_r0 : g_r1;
    float*       dst = (STEP == 1) ? g_r1 : g_r2;
    int tl = g_tails[n], r = g_rels[n];
    float hv = g_hidden[((STEP - 1) * E + hn) * LL + lane]
             * g_wp[(STEP * LL + lane) * NRELS + r];
#pragma unroll
    for (int b = 0; b < B; b++) {
        if (act & (1 << b)) {
            float v = src[(hn * B + b) * LL + lane];
            if (v != 0.f) {
                float x = v * hv;
                if (STEP == 1) x *= g_hidx[b * LL + lane];
                atomicAdd(&dst[(tl * B + b) * LL + lane], x);
            }
        }
    }
    if (lane == 0) {
        if (STEP == 1) atomicOr(&g_act1[tl], act);      // superset is safe
        else           atomicOr(&g_act2[tl], act);
    }
}

// ======== K6: epilogue with activity skip ========
__global__ void k_out(float* __restrict__ out) {
    int idx = blockIdx.x * 8 + (threadIdx.x >> 5);   // warp per (b,e)
    if (idx >= B * E) return;
    int lane = threadIdx.x & 31;
    int e = idx % E, b = idx / E;
    if (!(g_act2[e] & (1 << b))) { if (lane == 0) out[b * E + e] = 0.f; return; }
    float v = g_r2[(e * B + b) * LL + lane] * g_hidden[(2 * E + e) * LL + lane] * g_tanhw[lane];
#pragma unroll
    for (int o = 16; o > 0; o >>= 1) v += __shfl_down_sync(0xffffffffu, v, o);
    if (lane == 0) out[b * E + e] = v;
}

extern "C" void kernel_launch(void* const* d_in, const int* in_sizes, int n_in,
                              void* d_out, int out_size) {
    const float* inx    = (const float*)d_in[0];   // input_x   [8,2000]
    const float* tmat   = (const float*)d_in[1];   // type_mat  [2000,16]
    const float* e2t    = (const float*)d_in[2];   // e2triple  [2000,10000]
    const float* t2e    = (const float*)d_in[3];   // triple2e  [10000,2000]
    const float* t2r    = (const float*)d_in[4];   // triple2r  [10000,25]
    const float* w      = (const float*)d_in[5];   // [3,32,25]
    const float* weight = (const float*)d_in[6];   // [32,1]
    const float* h      = (const float*)d_in[7];   // [3,32,24]
    const float* hx     = (const float*)d_in[8];   // [32,24]
    const float* htype  = (const float*)d_in[9];   // [3,32,16]
    const float* hxtype = (const float*)d_in[10];  // [32,16]
    const float* alpha  = (const float*)d_in[11];  // [3,32]
    const float* beta   = (const float*)d_in[12];  // [3,32]
    const float* alphax = (const float*)d_in[13];  // [32]
    const float* betax  = (const float*)d_in[14];  // [32]
    float* out = (float*)d_out;

    k_extract<<<2048, 256>>>(inx, tmat, (const float4*)e2t, (const float4*)t2e, t2r);
    k_flags<<<41, 256>>>(w, weight);
    k_gates<<<751 + 1250, 256>>>(h, htype, alpha, beta, hx, hxtype, alphax, betax);
    k_prop<1><<<1250, 256>>>();   // r0 -> r1: hidden0 * hidden_x, wp1
    k_prop<2><<<1250, 256>>>();   // r1 -> r2: hidden1, wp2
    k_out<<<2000, 256>>>(out);
}